// round 16
// baseline (speedup 1.0000x reference)
#include <cuda_runtime.h>
#include <cuda_fp16.h>
#include <math.h>
#include <stdint.h>

#define BB 4096
#define DD 256
#define TT 64

// ================= PTX helpers (baseline ISA only) =================
__device__ __forceinline__ uint32_t smem_u32(const void* p) {
    uint32_t a;
    asm("{ .reg .u64 t; cvta.to.shared.u64 t, %1; cvt.u32.u64 %0, t; }" : "=r"(a) : "l"(p));
    return a;
}
__device__ __forceinline__ void cp16(uint32_t saddr, const void* g) {
    asm volatile("cp.async.cg.shared.global [%0], [%1], 16;" :: "r"(saddr), "l"(g));
}
__device__ __forceinline__ void ldsm4(uint32_t* r, uint32_t addr) {
    asm volatile("ldmatrix.sync.aligned.m8n8.x4.shared.b16 {%0,%1,%2,%3}, [%4];"
        : "=r"(r[0]), "=r"(r[1]), "=r"(r[2]), "=r"(r[3]) : "r"(addr));
}
__device__ __forceinline__ void mma16816(float* c, const uint32_t* a, uint32_t b0, uint32_t b1) {
    asm volatile("mma.sync.aligned.m16n8k16.row.col.f32.f16.f16.f32 "
        "{%0,%1,%2,%3}, {%4,%5,%6,%7}, {%8,%9}, {%0,%1,%2,%3};"
        : "+f"(c[0]), "+f"(c[1]), "+f"(c[2]), "+f"(c[3])
        : "r"(a[0]), "r"(a[1]), "r"(a[2]), "r"(a[3]), "r"(b0), "r"(b1));
}

// ================= scratch pool =================
static constexpr size_t SZ_XG  = (size_t)BB * 768 * 2;
static constexpr size_t SZ_XS  = (size_t)BB * 512 * 2;
static constexpr size_t SZ_BD  = (size_t)BB * 256 * 2;
static constexpr size_t SZ_Q0  = (size_t)2 * BB * 256 * 2;
static constexpr size_t SZ_BDF = (size_t)BB * 256 * 4;

static constexpr size_t O_XG   = 0;
static constexpr size_t O_XE   = O_XG  + SZ_XG;
static constexpr size_t O_XQS  = O_XE  + SZ_XG;
static constexpr size_t O_XRS  = O_XQS + SZ_XS;
static constexpr size_t O_XPL  = O_XRS + SZ_XS;
static constexpr size_t O_Q0H  = O_XPL + SZ_XS;
static constexpr size_t O_GHH  = O_Q0H + SZ_Q0;
static constexpr size_t O_E0H  = O_GHH + SZ_BD;
static constexpr size_t O_QSH  = O_E0H + SZ_BD;
static constexpr size_t O_RSH  = O_QSH + SZ_BD;
static constexpr size_t O_QSF  = O_RSH + SZ_BD;
static constexpr size_t O_RSF  = O_QSF + SZ_BDF;
static constexpr size_t SZ_W768 = (size_t)768 * 768 * 2;
static constexpr size_t SZ_W512 = (size_t)768 * 512 * 2;
static constexpr size_t SZ_W256 = (size_t)768 * 256 * 2;
static constexpr size_t O_WGIH = O_RSF + SZ_BDF;
static constexpr size_t O_WGHH = O_WGIH + SZ_W768;
static constexpr size_t O_WPIH = O_WGHH + SZ_W256;
static constexpr size_t O_WPHH = O_WPIH + SZ_W512;
static constexpr size_t O_WLIH = O_WPHH + SZ_W256;
static constexpr size_t O_WLHH = O_WLIH + SZ_W512;
static constexpr size_t O_WRIH = O_WLHH + SZ_W256;
static constexpr size_t O_WRHH = O_WRIH + SZ_W512;
static constexpr size_t O_WEIH = O_WRHH + SZ_W256;
static constexpr size_t O_WEHH = O_WEIH + SZ_W768;
static constexpr size_t O_SELROW = O_WEHH + SZ_W256;
static constexpr size_t O_QMIDX  = O_SELROW + BB * 4;
static constexpr size_t POOL_SZ  = O_QMIDX + BB * 4;

__device__ __align__(1024) unsigned char g_pool[POOL_SZ];

// ================= conv_all: f32 -> fp16 =================
struct ConvSeg { const float* src; __half* hi; int nblk; };
struct ConvTable { ConvSeg s[13]; };

__global__ void conv_all_kernel(ConvTable t) {
    int blk = blockIdx.x;
    #pragma unroll 1
    for (int i = 0; i < 13; i++) {
        int nb = t.s[i].nblk;
        if (blk < nb) {
            int idx = blk * 1024 + threadIdx.x * 4;
            float4 v = *(const float4*)(t.s[i].src + idx);
            __half2 hv0, hv1;
            hv0.x = __float2half(v.x); hv0.y = __float2half(v.y);
            hv1.x = __float2half(v.z); hv1.y = __float2half(v.w);
            *(__half2*)(t.s[i].hi + idx)     = hv0;
            *(__half2*)(t.s[i].hi + idx + 2) = hv1;
            return;
        }
        blk -= nb;
    }
}

// ================= prep =================
__global__ void prep_kernel(const float* __restrict__ U, const float* __restrict__ qmask,
                            const float* __restrict__ q0, const float* __restrict__ r0,
                            float* __restrict__ qsf, float* __restrict__ rsf,
                            __half* qsh, __half* rsh,
                            __half* xg, __half* xqs, __half* xrs, __half* xpl, __half* xe,
                            int* __restrict__ selrow, int* __restrict__ qmidx) {
    int i = blockIdx.x * 256 + threadIdx.x;
    int b = i >> 8, d = i & 255;
    int qm = (qmask[b * 2 + 1] > qmask[b * 2]) ? 1 : 0;
    if (d == 0) { qmidx[b] = qm; selrow[b] = b * 2 + qm; }
    float q = q0[(size_t)(b * 2 + qm) * DD + d];
    float r = r0[(size_t)(b * 2 + qm) * DD + d];
    float u = U[i];
    qsf[i] = q; rsf[i] = r;
    qsh[i] = __float2half(q);
    rsh[i] = __float2half(r);
    size_t o = (size_t)b * 768 + d;
    xg[o]       = __float2half(q);
    xg[o + 256] = __float2half(r);
    xg[o + 512] = __float2half(u);
    size_t o2 = (size_t)b * 512 + 256 + d;
    __half uh = __float2half(u);
    xqs[o2] = uh;
    xrs[o2] = uh;
    xpl[o2] = uh;
    xe[o]   = uh;   // xe seg0 = U
}

// ================= attention =================
__global__ void att_kernel(const float* __restrict__ gh, const float* __restrict__ attw,
                           __half* __restrict__ xrs, float* __restrict__ alpha_out) {
    extern __shared__ float sh[];
    __shared__ float s_aw[DD];
    __shared__ float s_scale[TT];
    __shared__ float s_alpha[TT];
    int b = blockIdx.x, tid = threadIdx.x;
    s_aw[tid] = attw[tid];
    for (int t = 0; t < TT; t++)
        sh[t * DD + tid] = gh[((size_t)t * BB + b) * DD + tid];
    __syncthreads();
    int w = tid >> 5, lane = tid & 31;
    for (int t = w; t < TT; t += 8) {
        float s = 0.f;
        #pragma unroll
        for (int i = 0; i < 8; i++) s += sh[t * DD + lane + i * 32] * s_aw[lane + i * 32];
        #pragma unroll
        for (int o = 16; o > 0; o >>= 1) s += __shfl_down_sync(0xffffffffu, s, o);
        if (lane == 0) s_scale[t] = s;
    }
    __syncthreads();
    if (w == 0) {
        float v0 = s_scale[lane], v1 = s_scale[lane + 32];
        float m = fmaxf(v0, v1);
        #pragma unroll
        for (int o = 16; o > 0; o >>= 1) m = fmaxf(m, __shfl_xor_sync(0xffffffffu, m, o));
        float e0 = expf(v0 - m), e1 = expf(v1 - m);
        float s = e0 + e1;
        #pragma unroll
        for (int o = 16; o > 0; o >>= 1) s += __shfl_xor_sync(0xffffffffu, s, o);
        float inv = 1.f / s;
        s_alpha[lane] = e0 * inv;
        s_alpha[lane + 32] = e1 * inv;
        alpha_out[(size_t)b * TT + lane] = e0 * inv;
        alpha_out[(size_t)b * TT + lane + 32] = e1 * inv;
    }
    __syncthreads();
    float acc = 0.f;
    for (int t = 0; t < TT; t++) acc += s_alpha[t] * sh[t * DD + tid];
    xrs[(size_t)b * 512 + tid] = __float2half(acc);
}

// ================= fused GRU — fp16, 128-thread CTA, 64x32 tile =================
// 4 warps = 2(m) x 2(n); warp tile m32n16. 5 CTAs/SM target (regs capped 102).
// Stage (K=32): A (64r x 80B = 5120) + W (3 gates x 32r x 80B = 7680) = 12800 B.
// Double buffer = 25600 B. Per k16: 2 A-LDSM + 3 B-LDSM, 12 MMA per warp.
#define AREG  5120
#define WTILE 2560
#define STAGE_SB 12800
#define GRU_SMEM (2 * STAGE_SB)

#define GATE2(ACCP, AF, BR) do { \
    mma16816((ACCP),     (AF), (BR)[0], (BR)[1]); \
    mma16816((ACCP) + 4, (AF), (BR)[2], (BR)[3]); \
} while (0)

__global__ __launch_bounds__(128, 5) void gru_mma_kernel(
    const __half* __restrict__ X, int K, int xshift,
    const __half* __restrict__ H, const float* __restrict__ Hf,
    const __half* __restrict__ Wih, const __half* __restrict__ Whh,
    const float* __restrict__ bih, const float* __restrict__ bhh,
    float* __restrict__ Out, const int* __restrict__ out_rows,
    const int* __restrict__ selrow, int zero_other,
    __half* __restrict__ x1, int x1_stride, int x1_off, int x1_sel,
    __half* __restrict__ x2, int x2_stride, int x2_off)
{
    extern __shared__ __align__(16) char dsm[];
    const uint32_t smb = smem_u32(dsm);

    const int tid = threadIdx.x;
    const int wid = tid >> 5, lane = tid & 31;
    const int warp_m = wid & 1, warp_n = wid >> 1;   // 2 m-warps x 2 n-warps
    const int row0 = blockIdx.x * 64, c0 = blockIdx.y * 32;

    const int nch0 = K / 32;
    const int ntot = nch0 + 8;

    float a0[16] = {}, a1[16] = {}, a2[16] = {}, a3[16] = {};

    // ---- loader setup: 5 vectors/thread/chunk (640 total) ----
    uint32_t sOff[5];
    const __half* gp[5];
    int greg[5], grow[5], ggate[5], gc[5];
    #pragma unroll
    for (int j = 0; j < 5; j++) {
        int v = tid + 128 * j;            // 0..639
        if (v < 256) {                    // A region: 64 rows x 4 vec
            int row = v >> 2, c = v & 3;
            sOff[j] = (uint32_t)row * 80 + c * 16;
            greg[j] = 0; grow[j] = row; ggate[j] = 0; gc[j] = c;
            gp[j] = X + (size_t)((row0 + row) >> xshift) * K + c * 8;
        } else {                          // W region: 96 rows x 4 vec
            int u = v - 256;
            int wrow = u >> 2, c = u & 3;
            int gate = wrow >> 5, r = wrow & 31;
            sOff[j] = AREG + (uint32_t)gate * WTILE + (uint32_t)r * 80 + c * 16;
            greg[j] = 1; grow[j] = r; ggate[j] = gate; gc[j] = c;
            gp[j] = Wih + (size_t)(gate * 256 + c0 + r) * K + c * 8;
        }
    }

    // ---- ldsm lane offsets (relative to stage base) ----
    const uint32_t AOFF = ((uint32_t)(warp_m * 32 + (lane & 7) + ((lane >> 3) & 1) * 8)) * 80
                        + (uint32_t)(lane >> 4) * 16;
    const uint32_t BOFF = AREG
                        + ((uint32_t)(warp_n * 16 + (lane & 7) + (lane >> 4) * 8)) * 80
                        + (uint32_t)((lane >> 3) & 1) * 16;

    #define PREF(SOFF) do { \
        cp16(smb + (SOFF) + sOff[0], gp[0]); \
        cp16(smb + (SOFF) + sOff[1], gp[1]); \
        cp16(smb + (SOFF) + sOff[2], gp[2]); \
        cp16(smb + (SOFF) + sOff[3], gp[3]); \
        cp16(smb + (SOFF) + sOff[4], gp[4]); \
        gp[0] += 32; gp[1] += 32; gp[2] += 32; gp[3] += 32; gp[4] += 32; \
    } while (0)

    PREF(0);
    asm volatile("cp.async.commit_group;");

    #pragma unroll 1
    for (int i = 0; i < ntot; i++) {
        asm volatile("cp.async.wait_group 0;");
        __syncthreads();   // publish stage i; certify other stage consumed

        if (i + 1 < ntot) {
            if (i + 1 == nch0) {
                #pragma unroll
                for (int j = 0; j < 5; j++) {
                    if (greg[j] == 0)
                        gp[j] = H + (size_t)(row0 + grow[j]) * 256 + gc[j] * 8;
                    else
                        gp[j] = Whh + (size_t)(ggate[j] * 256 + c0 + grow[j]) * 256 + gc[j] * 8;
                }
            }
            PREF(((i + 1) & 1) ? STAGE_SB : 0u);
            asm volatile("cp.async.commit_group;");
        }

        const uint32_t base = smb + ((i & 1) ? STAGE_SB : 0u);
        #pragma unroll
        for (int s = 0; s < 2; s++) {
            const uint32_t ka = (uint32_t)s * 32;
            uint32_t ah0[4], ah1[4], bf[4];
            ldsm4(ah0, base + AOFF + ka);
            ldsm4(ah1, base + AOFF + 1280 + ka);          // +16 rows
            // gate 0 -> a0
            ldsm4(bf, base + BOFF + ka);
            GATE2(a0,     ah0, bf); GATE2(a0 + 8, ah1, bf);
            // gate 1 -> a1
            ldsm4(bf, base + BOFF + WTILE + ka);
            GATE2(a1,     ah0, bf); GATE2(a1 + 8, ah1, bf);
            // gate 2 -> a2 (phase 0) or a3 (phase 1)
            ldsm4(bf, base + BOFF + 2 * WTILE + ka);
            if (i < nch0) {
                GATE2(a2,     ah0, bf); GATE2(a2 + 8, ah1, bf);
            } else {
                GATE2(a3,     ah0, bf); GATE2(a3 + 8, ah1, bf);
            }
        }
    }
    #undef PREF

    // ---- epilogue ----
    #pragma unroll
    for (int msub = 0; msub < 2; msub++) {
        const int mrowb = row0 + warp_m * 32 + msub * 16 + (lane >> 2);
        #pragma unroll
        for (int half = 0; half < 2; half++) {
            int m = mrowb + half * 8;
            int orow = out_rows ? out_rows[m] : m;
            const float* hrow = Hf + (size_t)m * 256;
            float* op = Out + (size_t)orow * 256;
            float* oo = zero_other ? (Out + (size_t)(orow ^ 1) * 256) : nullptr;
            int x1b = x1_sel ? (m >> 1) : m;
            bool x1ok = x1 && (!x1_sel || (selrow[x1b] == m));
            #pragma unroll
            for (int nt = 0; nt < 2; nt++) {
                #pragma unroll
                for (int e = 0; e < 2; e++) {
                    int col = c0 + warp_n * 16 + (lane & 3) * 2 + nt * 8 + e;
                    int d = msub * 8 + nt * 4 + half * 2 + e;
                    float ar = a0[d] + bih[col] + bhh[col];
                    float az = a1[d] + bih[256 + col] + bhh[256 + col];
                    float r = 1.f / (1.f + expf(-ar));
                    float z = 1.f / (1.f + expf(-az));
                    float n = tanhf(a2[d] + bih[512 + col] + r * (a3[d] + bhh[512 + col]));
                    float v = (1.f - z) * n + z * hrow[col];
                    op[col] = v;
                    if (oo) oo[col] = 0.f;
                    if (x1ok) x1[(size_t)x1b * x1_stride + x1_off + col] = __float2half(v);
                    if (x2)   x2[(size_t)m * x2_stride + x2_off + col]   = __float2half(v);
                }
            }
        }
    }
}

// ================= launch =================
extern "C" void kernel_launch(void* const* d_in, const int* in_sizes, int n_in,
                              void* d_out, int out_size) {
    const float* U      = (const float*)d_in[0];
    const float* qmask  = (const float*)d_in[1];
    const float* g_hist = (const float*)d_in[2];
    const float* q0     = (const float*)d_in[3];
    const float* r0     = (const float*)d_in[4];
    const float* e0     = (const float*)d_in[5];
    const float* g_wih  = (const float*)d_in[6];
    const float* g_whh  = (const float*)d_in[7];
    const float* g_bih  = (const float*)d_in[8];
    const float* g_bhh  = (const float*)d_in[9];
    const float* p_wih  = (const float*)d_in[10];
    const float* p_whh  = (const float*)d_in[11];
    const float* p_bih  = (const float*)d_in[12];
    const float* p_bhh  = (const float*)d_in[13];
    const float* pl_wih = (const float*)d_in[14];
    const float* pl_whh = (const float*)d_in[15];
    const float* pl_bih = (const float*)d_in[16];
    const float* pl_bhh = (const float*)d_in[17];
    const float* r_wih  = (const float*)d_in[18];
    const float* r_whh  = (const float*)d_in[19];
    const float* r_bih  = (const float*)d_in[20];
    const float* r_bhh  = (const float*)d_in[21];
    const float* e_wih  = (const float*)d_in[22];
    const float* e_whh  = (const float*)d_in[23];
    const float* e_bih  = (const float*)d_in[24];
    const float* e_bhh  = (const float*)d_in[25];
    const float* att_w  = (const float*)d_in[26];

    float* out = (float*)d_out;
    float* o_g = out;
    float* o_q = out + 1048576;
    float* o_r = out + 3145728;
    float* o_e = out + 5242880;
    float* o_a = out + 6291456;

    void* poolv;
    cudaGetSymbolAddress(&poolv, g_pool);
    char* pool = (char*)poolv;
    #define HF(off) ((__half*)(pool + (off)))
    #define FP(off) ((float*)(pool + (off)))
    int* selrow = (int*)(pool + O_SELROW);
    int* qmidx  = (int*)(pool + O_QMIDX);

    cudaFuncSetAttribute(att_kernel, cudaFuncAttributeMaxDynamicSharedMemorySize,
                         TT * DD * (int)sizeof(float));
    cudaFuncSetAttribute(gru_mma_kernel, cudaFuncAttributeMaxDynamicSharedMemorySize, GRU_SMEM);

    const float* ghl = g_hist + (size_t)63 * BB * DD;

    // 1) conversions
    ConvTable ct;
    int ti = 0, total_blk = 0;
    auto addseg = [&](const float* s, size_t oh, int n) {
        ct.s[ti].src = s; ct.s[ti].hi = HF(oh);
        ct.s[ti].nblk = n / 1024; total_blk += n / 1024; ti++;
    };
    addseg(g_wih,  O_WGIH, 768 * 768);
    addseg(g_whh,  O_WGHH, 768 * 256);
    addseg(p_wih,  O_WPIH, 768 * 512);
    addseg(p_whh,  O_WPHH, 768 * 256);
    addseg(pl_wih, O_WLIH, 768 * 512);
    addseg(pl_whh, O_WLHH, 768 * 256);
    addseg(r_wih,  O_WRIH, 768 * 512);
    addseg(r_whh,  O_WRHH, 768 * 256);
    addseg(e_wih,  O_WEIH, 768 * 768);
    addseg(e_whh,  O_WEHH, 768 * 256);
    addseg(q0,     O_Q0H,  2 * BB * 256);
    addseg(ghl,    O_GHH,  BB * 256);
    addseg(e0,     O_E0H,  BB * 256);
    conv_all_kernel<<<total_blk, 256>>>(ct);

    // 2) prep
    prep_kernel<<<BB, 256>>>(U, qmask, q0, r0,
        FP(O_QSF), FP(O_RSF), HF(O_QSH), HF(O_RSH),
        HF(O_XG), HF(O_XQS), HF(O_XRS), HF(O_XPL), HF(O_XE),
        selrow, qmidx);

    // 3) attention -> xrs first half + alpha
    att_kernel<<<BB, 256, TT * DD * sizeof(float)>>>(g_hist, att_w, HF(O_XRS), o_a);

    // 4) g GRU: K=768; epilogue writes xqs[0:256] and xe[512:768]
    gru_mma_kernel<<<dim3(BB / 64, 8), 128, GRU_SMEM>>>(
        HF(O_XG), 768, 0,
        HF(O_GHH), ghl,
        HF(O_WGIH), HF(O_WGHH),
        g_bih, g_bhh, o_g, nullptr,
        nullptr, 0,
        HF(O_XQS), 512, 0, 0,
        HF(O_XE), 768, 512);

    // 5) qs GRU: 8192 rows; epilogue writes xpl[0:256] for selected rows
    gru_mma_kernel<<<dim3(2 * BB / 64, 8), 128, GRU_SMEM>>>(
        HF(O_XQS), 512, 1,
        HF(O_Q0H), q0,
        HF(O_WPIH), HF(O_WPHH),
        p_bih, p_bhh, o_q, nullptr,
        selrow, 0,
        HF(O_XPL), 512, 0, 1,
        nullptr, 0, 0);

    // 6) rs GRU: selected rows, scatter + zero sibling row   [ncu slot 6]
    gru_mma_kernel<<<dim3(BB / 64, 8), 128, GRU_SMEM>>>(
        HF(O_XRS), 512, 0,
        HF(O_RSH), FP(O_RSF),
        HF(O_WRIH), HF(O_WRHH),
        r_bih, r_bhh, o_r, selrow,
        nullptr, 1,
        nullptr, 0, 0, 0,
        nullptr, 0, 0);

    // 7) ql GRU: selected rows, scatter into q_; epilogue writes xe[256:512]
    gru_mma_kernel<<<dim3(BB / 64, 8), 128, GRU_SMEM>>>(
        HF(O_XPL), 512, 0,
        HF(O_QSH), FP(O_QSF),
        HF(O_WLIH), HF(O_WLHH),
        pl_bih, pl_bhh, o_q, selrow,
        nullptr, 0,
        HF(O_XE), 768, 256, 0,
        nullptr, 0, 0);

    // 8) e GRU: K=768
    gru_mma_kernel<<<dim3(BB / 64, 8), 128, GRU_SMEM>>>(
        HF(O_XE), 768, 0,
        HF(O_E0H), e0,
        HF(O_WEIH), HF(O_WEHH),
        e_bih, e_bhh, o_e, nullptr,
        nullptr, 0,
        nullptr, 0, 0, 0,
        nullptr, 0, 0);
    #undef HF
    #undef FP
}

// round 17
// speedup vs baseline: 1.0971x; 1.0971x over previous
#include <cuda_runtime.h>
#include <cuda_fp16.h>
#include <math.h>
#include <stdint.h>

#define BB 4096
#define DD 256
#define TT 64

// ================= PTX helpers (baseline ISA only) =================
__device__ __forceinline__ uint32_t smem_u32(const void* p) {
    uint32_t a;
    asm("{ .reg .u64 t; cvta.to.shared.u64 t, %1; cvt.u32.u64 %0, t; }" : "=r"(a) : "l"(p));
    return a;
}
__device__ __forceinline__ void cp16(uint32_t saddr, const void* g) {
    asm volatile("cp.async.cg.shared.global [%0], [%1], 16;" :: "r"(saddr), "l"(g));
}
__device__ __forceinline__ void ldsm4(uint32_t* r, uint32_t addr) {
    asm volatile("ldmatrix.sync.aligned.m8n8.x4.shared.b16 {%0,%1,%2,%3}, [%4];"
        : "=r"(r[0]), "=r"(r[1]), "=r"(r[2]), "=r"(r[3]) : "r"(addr));
}
__device__ __forceinline__ void mma16816(float* c, const uint32_t* a, uint32_t b0, uint32_t b1) {
    asm volatile("mma.sync.aligned.m16n8k16.row.col.f32.f16.f16.f32 "
        "{%0,%1,%2,%3}, {%4,%5,%6,%7}, {%8,%9}, {%0,%1,%2,%3};"
        : "+f"(c[0]), "+f"(c[1]), "+f"(c[2]), "+f"(c[3])
        : "r"(a[0]), "r"(a[1]), "r"(a[2]), "r"(a[3]), "r"(b0), "r"(b1));
}

// ================= scratch pool =================
static constexpr size_t SZ_XG  = (size_t)BB * 768 * 2;
static constexpr size_t SZ_XS  = (size_t)BB * 512 * 2;
static constexpr size_t SZ_BD  = (size_t)BB * 256 * 2;
static constexpr size_t SZ_Q0  = (size_t)2 * BB * 256 * 2;
static constexpr size_t SZ_BDF = (size_t)BB * 256 * 4;

static constexpr size_t O_XG   = 0;
static constexpr size_t O_XE   = O_XG  + SZ_XG;
static constexpr size_t O_XQS  = O_XE  + SZ_XG;
static constexpr size_t O_XRS  = O_XQS + SZ_XS;
static constexpr size_t O_XPL  = O_XRS + SZ_XS;
static constexpr size_t O_Q0H  = O_XPL + SZ_XS;
static constexpr size_t O_GHH  = O_Q0H + SZ_Q0;
static constexpr size_t O_E0H  = O_GHH + SZ_BD;
static constexpr size_t O_QSH  = O_E0H + SZ_BD;
static constexpr size_t O_RSH  = O_QSH + SZ_BD;
static constexpr size_t O_QSF  = O_RSH + SZ_BD;
static constexpr size_t O_RSF  = O_QSF + SZ_BDF;
static constexpr size_t SZ_W768 = (size_t)768 * 768 * 2;
static constexpr size_t SZ_W512 = (size_t)768 * 512 * 2;
static constexpr size_t SZ_W256 = (size_t)768 * 256 * 2;
static constexpr size_t O_WGIH = O_RSF + SZ_BDF;
static constexpr size_t O_WGHH = O_WGIH + SZ_W768;
static constexpr size_t O_WPIH = O_WGHH + SZ_W256;
static constexpr size_t O_WPHH = O_WPIH + SZ_W512;
static constexpr size_t O_WLIH = O_WPHH + SZ_W256;
static constexpr size_t O_WLHH = O_WLIH + SZ_W512;
static constexpr size_t O_WRIH = O_WLHH + SZ_W256;
static constexpr size_t O_WRHH = O_WRIH + SZ_W512;
static constexpr size_t O_WEIH = O_WRHH + SZ_W256;
static constexpr size_t O_WEHH = O_WEIH + SZ_W768;
static constexpr size_t O_SELROW = O_WEHH + SZ_W256;
static constexpr size_t O_QMIDX  = O_SELROW + BB * 4;
static constexpr size_t POOL_SZ  = O_QMIDX + BB * 4;

__device__ __align__(1024) unsigned char g_pool[POOL_SZ];

// ================= conv_all: f32 -> fp16 =================
struct ConvSeg { const float* src; __half* hi; int nblk; };
struct ConvTable { ConvSeg s[13]; };

__global__ void conv_all_kernel(ConvTable t) {
    int blk = blockIdx.x;
    #pragma unroll 1
    for (int i = 0; i < 13; i++) {
        int nb = t.s[i].nblk;
        if (blk < nb) {
            int idx = blk * 1024 + threadIdx.x * 4;
            float4 v = *(const float4*)(t.s[i].src + idx);
            __half2 hv0, hv1;
            hv0.x = __float2half(v.x); hv0.y = __float2half(v.y);
            hv1.x = __float2half(v.z); hv1.y = __float2half(v.w);
            *(__half2*)(t.s[i].hi + idx)     = hv0;
            *(__half2*)(t.s[i].hi + idx + 2) = hv1;
            return;
        }
        blk -= nb;
    }
}

// ================= prep =================
__global__ void prep_kernel(const float* __restrict__ U, const float* __restrict__ qmask,
                            const float* __restrict__ q0, const float* __restrict__ r0,
                            float* __restrict__ qsf, float* __restrict__ rsf,
                            __half* qsh, __half* rsh,
                            __half* xg, __half* xqs, __half* xrs, __half* xpl, __half* xe,
                            int* __restrict__ selrow, int* __restrict__ qmidx) {
    int i = blockIdx.x * 256 + threadIdx.x;
    int b = i >> 8, d = i & 255;
    int qm = (qmask[b * 2 + 1] > qmask[b * 2]) ? 1 : 0;
    if (d == 0) { qmidx[b] = qm; selrow[b] = b * 2 + qm; }
    float q = q0[(size_t)(b * 2 + qm) * DD + d];
    float r = r0[(size_t)(b * 2 + qm) * DD + d];
    float u = U[i];
    qsf[i] = q; rsf[i] = r;
    qsh[i] = __float2half(q);
    rsh[i] = __float2half(r);
    size_t o = (size_t)b * 768 + d;
    xg[o]       = __float2half(q);
    xg[o + 256] = __float2half(r);
    xg[o + 512] = __float2half(u);
    size_t o2 = (size_t)b * 512 + 256 + d;
    __half uh = __float2half(u);
    xqs[o2] = uh;
    xrs[o2] = uh;
    xpl[o2] = uh;
    xe[o]   = uh;   // xe seg0 = U
}

// ================= attention =================
__global__ void att_kernel(const float* __restrict__ gh, const float* __restrict__ attw,
                           __half* __restrict__ xrs, float* __restrict__ alpha_out) {
    extern __shared__ float sh[];
    __shared__ float s_aw[DD];
    __shared__ float s_scale[TT];
    __shared__ float s_alpha[TT];
    int b = blockIdx.x, tid = threadIdx.x;
    s_aw[tid] = attw[tid];
    for (int t = 0; t < TT; t++)
        sh[t * DD + tid] = gh[((size_t)t * BB + b) * DD + tid];
    __syncthreads();
    int w = tid >> 5, lane = tid & 31;
    for (int t = w; t < TT; t += 8) {
        float s = 0.f;
        #pragma unroll
        for (int i = 0; i < 8; i++) s += sh[t * DD + lane + i * 32] * s_aw[lane + i * 32];
        #pragma unroll
        for (int o = 16; o > 0; o >>= 1) s += __shfl_down_sync(0xffffffffu, s, o);
        if (lane == 0) s_scale[t] = s;
    }
    __syncthreads();
    if (w == 0) {
        float v0 = s_scale[lane], v1 = s_scale[lane + 32];
        float m = fmaxf(v0, v1);
        #pragma unroll
        for (int o = 16; o > 0; o >>= 1) m = fmaxf(m, __shfl_xor_sync(0xffffffffu, m, o));
        float e0 = expf(v0 - m), e1 = expf(v1 - m);
        float s = e0 + e1;
        #pragma unroll
        for (int o = 16; o > 0; o >>= 1) s += __shfl_xor_sync(0xffffffffu, s, o);
        float inv = 1.f / s;
        s_alpha[lane] = e0 * inv;
        s_alpha[lane + 32] = e1 * inv;
        alpha_out[(size_t)b * TT + lane] = e0 * inv;
        alpha_out[(size_t)b * TT + lane + 32] = e1 * inv;
    }
    __syncthreads();
    float acc = 0.f;
    for (int t = 0; t < TT; t++) acc += s_alpha[t] * sh[t * DD + tid];
    xrs[(size_t)b * 512 + tid] = __float2half(acc);
}

// ================= fused GRU — fp16, K=64 chunks, m32n16 warp tile =================
// Block tile: 64 rows x 64 out-cols; 8 warps = 2(m) x 4(n); warp tile 32x16.
// Chunk K=64: row = 128B payload + 16B pad = 144B stride (cp.async-aligned;
// 144*r mod 128 = 16r -> 8 distinct banks, LDSM conflict-free).
// Stage: A (64r) + W (3 gates x 64r) = 4 x 9216 = 36864 B; double buffer 73728 B.
// 12 chunks total for K=512 (8 input + 4 hidden); halved barrier/loader overhead.
#define RT144 144
#define GTILE 9216
#define AREG  9216
#define STAGE_SB 36864
#define GRU_SMEM (2 * STAGE_SB)

#define GATE2(ACCP, AF, BR) do { \
    mma16816((ACCP),     (AF), (BR)[0], (BR)[1]); \
    mma16816((ACCP) + 4, (AF), (BR)[2], (BR)[3]); \
} while (0)

__global__ __launch_bounds__(256, 2) void gru_mma_kernel(
    const __half* __restrict__ X, int K, int xshift,
    const __half* __restrict__ H, const float* __restrict__ Hf,
    const __half* __restrict__ Wih, const __half* __restrict__ Whh,
    const float* __restrict__ bih, const float* __restrict__ bhh,
    float* __restrict__ Out, const int* __restrict__ out_rows,
    const int* __restrict__ selrow, int zero_other,
    __half* __restrict__ x1, int x1_stride, int x1_off, int x1_sel,
    __half* __restrict__ x2, int x2_stride, int x2_off)
{
    extern __shared__ __align__(16) char dsm[];
    const uint32_t smb = smem_u32(dsm);

    const int tid = threadIdx.x;
    const int wid = tid >> 5, lane = tid & 31;
    const int warp_m = wid & 1, warp_n = wid >> 1;   // 2 m-warps x 4 n-warps
    const int row0 = blockIdx.x * 64, c0 = blockIdx.y * 64;

    const int nch0 = K / 64;            // input-GEMM chunks
    const int ntot = nch0 + 4;          // + hidden chunks (256/64)

    float a0[16] = {}, a1[16] = {}, a2[16] = {}, a3[16] = {};

    // ---- loader: 2 pointers + strides; 8 vecs/thread/chunk ----
    // vec j: row = (tid>>3) + 32*j'; c = tid&7 fixed.
    const int r8 = tid >> 3, cv = tid & 7;
    const uint32_t sA = (uint32_t)r8 * RT144 + cv * 16;       // A region base
    const uint32_t sW = AREG + (uint32_t)r8 * RT144 + cv * 16;
    const __half* pa = X + (size_t)((row0 + r8) >> xshift) * K + cv * 8;
    const __half* pa32 = X + (size_t)((row0 + r8 + 32) >> xshift) * K + cv * 8;
    const __half* pw = Wih + (size_t)(c0 + r8) * K + cv * 8;
    size_t wg = (size_t)256 * K;     // gate stride (elems)
    size_t w32 = (size_t)32 * K;     // +32 rows stride

    // ---- ldsm lane offsets (relative to stage base) ----
    const uint32_t AOFF = ((uint32_t)(warp_m * 32 + (lane & 7) + ((lane >> 3) & 1) * 8)) * RT144
                        + (uint32_t)(lane >> 4) * 16;
    const uint32_t BOFF = AREG
                        + ((uint32_t)(warp_n * 16 + (lane & 7) + (lane >> 4) * 8)) * RT144
                        + (uint32_t)((lane >> 3) & 1) * 16;

    #define PREF(SOFF) do { \
        cp16(smb + (SOFF) + sA,              pa); \
        cp16(smb + (SOFF) + sA + 32 * RT144, pa32); \
        cp16(smb + (SOFF) + sW,                          pw); \
        cp16(smb + (SOFF) + sW + 32 * RT144,             pw + w32); \
        cp16(smb + (SOFF) + sW + GTILE,                  pw + wg); \
        cp16(smb + (SOFF) + sW + GTILE + 32 * RT144,     pw + wg + w32); \
        cp16(smb + (SOFF) + sW + 2 * GTILE,              pw + 2 * wg); \
        cp16(smb + (SOFF) + sW + 2 * GTILE + 32 * RT144, pw + 2 * wg + w32); \
        pa += 64; pa32 += 64; pw += 64; \
    } while (0)

    PREF(0);
    asm volatile("cp.async.commit_group;");

    #pragma unroll 1
    for (int i = 0; i < ntot; i++) {
        asm volatile("cp.async.wait_group 0;");
        __syncthreads();   // publish stage i; certify other stage consumed

        if (i + 1 < ntot) {
            if (i + 1 == nch0) {
                pa   = H + (size_t)(row0 + r8) * 256 + cv * 8;
                pa32 = H + (size_t)(row0 + r8 + 32) * 256 + cv * 8;
                pw   = Whh + (size_t)(c0 + r8) * 256 + cv * 8;
                wg = (size_t)256 * 256;
                w32 = (size_t)32 * 256;
            }
            PREF(((i + 1) & 1) ? STAGE_SB : 0u);
            asm volatile("cp.async.commit_group;");
        }

        const uint32_t base = smb + ((i & 1) ? STAGE_SB : 0u);
        #pragma unroll
        for (int s = 0; s < 4; s++) {
            const uint32_t ka = (uint32_t)s * 32;
            uint32_t ah0[4], ah1[4], bf[4];
            ldsm4(ah0, base + AOFF + ka);
            ldsm4(ah1, base + AOFF + 16 * RT144 + ka);    // +16 rows
            // gate 0 -> a0
            ldsm4(bf, base + BOFF + ka);
            GATE2(a0,     ah0, bf); GATE2(a0 + 8, ah1, bf);
            // gate 1 -> a1
            ldsm4(bf, base + BOFF + GTILE + ka);
            GATE2(a1,     ah0, bf); GATE2(a1 + 8, ah1, bf);
            // gate 2 -> a2 (phase 0) or a3 (phase 1)
            ldsm4(bf, base + BOFF + 2 * GTILE + ka);
            if (i < nch0) {
                GATE2(a2,     ah0, bf); GATE2(a2 + 8, ah1, bf);
            } else {
                GATE2(a3,     ah0, bf); GATE2(a3 + 8, ah1, bf);
            }
        }
    }
    #undef PREF

    // ---- epilogue ----
    #pragma unroll
    for (int msub = 0; msub < 2; msub++) {
        const int mrowb = row0 + warp_m * 32 + msub * 16 + (lane >> 2);
        #pragma unroll
        for (int half = 0; half < 2; half++) {
            int m = mrowb + half * 8;
            int orow = out_rows ? out_rows[m] : m;
            const float* hrow = Hf + (size_t)m * 256;
            float* op = Out + (size_t)orow * 256;
            float* oo = zero_other ? (Out + (size_t)(orow ^ 1) * 256) : nullptr;
            int x1b = x1_sel ? (m >> 1) : m;
            bool x1ok = x1 && (!x1_sel || (selrow[x1b] == m));
            #pragma unroll
            for (int nt = 0; nt < 2; nt++) {
                #pragma unroll
                for (int e = 0; e < 2; e++) {
                    int col = c0 + warp_n * 16 + (lane & 3) * 2 + nt * 8 + e;
                    int d = msub * 8 + nt * 4 + half * 2 + e;
                    float ar = a0[d] + bih[col] + bhh[col];
                    float az = a1[d] + bih[256 + col] + bhh[256 + col];
                    float r = 1.f / (1.f + expf(-ar));
                    float z = 1.f / (1.f + expf(-az));
                    float n = tanhf(a2[d] + bih[512 + col] + r * (a3[d] + bhh[512 + col]));
                    float v = (1.f - z) * n + z * hrow[col];
                    op[col] = v;
                    if (oo) oo[col] = 0.f;
                    if (x1ok) x1[(size_t)x1b * x1_stride + x1_off + col] = __float2half(v);
                    if (x2)   x2[(size_t)m * x2_stride + x2_off + col]   = __float2half(v);
                }
            }
        }
    }
}

// ================= launch =================
extern "C" void kernel_launch(void* const* d_in, const int* in_sizes, int n_in,
                              void* d_out, int out_size) {
    const float* U      = (const float*)d_in[0];
    const float* qmask  = (const float*)d_in[1];
    const float* g_hist = (const float*)d_in[2];
    const float* q0     = (const float*)d_in[3];
    const float* r0     = (const float*)d_in[4];
    const float* e0     = (const float*)d_in[5];
    const float* g_wih  = (const float*)d_in[6];
    const float* g_whh  = (const float*)d_in[7];
    const float* g_bih  = (const float*)d_in[8];
    const float* g_bhh  = (const float*)d_in[9];
    const float* p_wih  = (const float*)d_in[10];
    const float* p_whh  = (const float*)d_in[11];
    const float* p_bih  = (const float*)d_in[12];
    const float* p_bhh  = (const float*)d_in[13];
    const float* pl_wih = (const float*)d_in[14];
    const float* pl_whh = (const float*)d_in[15];
    const float* pl_bih = (const float*)d_in[16];
    const float* pl_bhh = (const float*)d_in[17];
    const float* r_wih  = (const float*)d_in[18];
    const float* r_whh  = (const float*)d_in[19];
    const float* r_bih  = (const float*)d_in[20];
    const float* r_bhh  = (const float*)d_in[21];
    const float* e_wih  = (const float*)d_in[22];
    const float* e_whh  = (const float*)d_in[23];
    const float* e_bih  = (const float*)d_in[24];
    const float* e_bhh  = (const float*)d_in[25];
    const float* att_w  = (const float*)d_in[26];

    float* out = (float*)d_out;
    float* o_g = out;
    float* o_q = out + 1048576;
    float* o_r = out + 3145728;
    float* o_e = out + 5242880;
    float* o_a = out + 6291456;

    void* poolv;
    cudaGetSymbolAddress(&poolv, g_pool);
    char* pool = (char*)poolv;
    #define HF(off) ((__half*)(pool + (off)))
    #define FP(off) ((float*)(pool + (off)))
    int* selrow = (int*)(pool + O_SELROW);
    int* qmidx  = (int*)(pool + O_QMIDX);

    cudaFuncSetAttribute(att_kernel, cudaFuncAttributeMaxDynamicSharedMemorySize,
                         TT * DD * (int)sizeof(float));
    cudaFuncSetAttribute(gru_mma_kernel, cudaFuncAttributeMaxDynamicSharedMemorySize, GRU_SMEM);

    const float* ghl = g_hist + (size_t)63 * BB * DD;

    // 1) conversions
    ConvTable ct;
    int ti = 0, total_blk = 0;
    auto addseg = [&](const float* s, size_t oh, int n) {
        ct.s[ti].src = s; ct.s[ti].hi = HF(oh);
        ct.s[ti].nblk = n / 1024; total_blk += n / 1024; ti++;
    };
    addseg(g_wih,  O_WGIH, 768 * 768);
    addseg(g_whh,  O_WGHH, 768 * 256);
    addseg(p_wih,  O_WPIH, 768 * 512);
    addseg(p_whh,  O_WPHH, 768 * 256);
    addseg(pl_wih, O_WLIH, 768 * 512);
    addseg(pl_whh, O_WLHH, 768 * 256);
    addseg(r_wih,  O_WRIH, 768 * 512);
    addseg(r_whh,  O_WRHH, 768 * 256);
    addseg(e_wih,  O_WEIH, 768 * 768);
    addseg(e_whh,  O_WEHH, 768 * 256);
    addseg(q0,     O_Q0H,  2 * BB * 256);
    addseg(ghl,    O_GHH,  BB * 256);
    addseg(e0,     O_E0H,  BB * 256);
    conv_all_kernel<<<total_blk, 256>>>(ct);

    // 2) prep
    prep_kernel<<<BB, 256>>>(U, qmask, q0, r0,
        FP(O_QSF), FP(O_RSF), HF(O_QSH), HF(O_RSH),
        HF(O_XG), HF(O_XQS), HF(O_XRS), HF(O_XPL), HF(O_XE),
        selrow, qmidx);

    // 3) attention -> xrs first half + alpha
    att_kernel<<<BB, 256, TT * DD * sizeof(float)>>>(g_hist, att_w, HF(O_XRS), o_a);

    // 4) g GRU: K=768; epilogue writes xqs[0:256] and xe[512:768]
    gru_mma_kernel<<<dim3(BB / 64, 4), 256, GRU_SMEM>>>(
        HF(O_XG), 768, 0,
        HF(O_GHH), ghl,
        HF(O_WGIH), HF(O_WGHH),
        g_bih, g_bhh, o_g, nullptr,
        nullptr, 0,
        HF(O_XQS), 512, 0, 0,
        HF(O_XE), 768, 512);

    // 5) qs GRU: 8192 rows; epilogue writes xpl[0:256] for selected rows
    gru_mma_kernel<<<dim3(2 * BB / 64, 4), 256, GRU_SMEM>>>(
        HF(O_XQS), 512, 1,
        HF(O_Q0H), q0,
        HF(O_WPIH), HF(O_WPHH),
        p_bih, p_bhh, o_q, nullptr,
        selrow, 0,
        HF(O_XPL), 512, 0, 1,
        nullptr, 0, 0);

    // 6) rs GRU: selected rows, scatter + zero sibling row   [ncu slot 6]
    gru_mma_kernel<<<dim3(BB / 64, 4), 256, GRU_SMEM>>>(
        HF(O_XRS), 512, 0,
        HF(O_RSH), FP(O_RSF),
        HF(O_WRIH), HF(O_WRHH),
        r_bih, r_bhh, o_r, selrow,
        nullptr, 1,
        nullptr, 0, 0, 0,
        nullptr, 0, 0);

    // 7) ql GRU: selected rows, scatter into q_; epilogue writes xe[256:512]
    gru_mma_kernel<<<dim3(BB / 64, 4), 256, GRU_SMEM>>>(
        HF(O_XPL), 512, 0,
        HF(O_QSH), FP(O_QSF),
        HF(O_WLIH), HF(O_WLHH),
        pl_bih, pl_bhh, o_q, selrow,
        nullptr, 0,
        HF(O_XE), 768, 256, 0,
        nullptr, 0, 0);

    // 8) e GRU: K=768
    gru_mma_kernel<<<dim3(BB / 64, 4), 256, GRU_SMEM>>>(
        HF(O_XE), 768, 0,
        HF(O_E0H), e0,
        HF(O_WEIH), HF(O_WEHH),
        e_bih, e_bhh, o_e, nullptr,
        nullptr, 0,
        nullptr, 0, 0, 0,
        nullptr, 0, 0);
    #undef HF
    #undef FP
}